// round 11
// baseline (speedup 1.0000x reference)
#include <cuda_runtime.h>
#include <cuda_bf16.h>
#include <mma.h>
#include <cstdint>

using namespace nvcuda;

#define N_NODES 50000
#define N_EDGES 600000
#define IN_CH 128
#define HID_CH 128
#define OUT_CH 64
#define NUM_GRAPHS 512

// ---------------- device scratch (zero-initialized at load; every call leaves
// g_cnt / g_pool / g_pcnt zeroed again, so replays are identical) ----------------
__device__ float g_t1[N_NODES * HID_CH];       // 25.6 MB (GEMM outputs, agg gathers)
__device__ __nv_bfloat16 g_ah[N_NODES * HID_CH];  // 12.8 MB: A-plane hi for next GEMM
__device__ __nv_bfloat16 g_al[N_NODES * HID_CH];  // 12.8 MB: A-plane lo
__device__ __nv_bfloat16 g_xh[N_NODES * HID_CH];  // x split planes
__device__ __nv_bfloat16 g_xl[N_NODES * HID_CH];
__device__ int   g_cnt[N_NODES];
__device__ float g_dinv[N_NODES];
__device__ int   g_rowptr[N_NODES + 1];
__device__ int   g_cursor[N_NODES];
__device__ int   g_csrsrc[N_EDGES];
__device__ float g_pool[NUM_GRAPHS * HID_CH];
__device__ float g_pcnt[NUM_GRAPHS];
__device__ __nv_bfloat16 g_wh1[HID_CH * HID_CH];   // W1^T hi, [n][k]
__device__ __nv_bfloat16 g_wl1[HID_CH * HID_CH];   // W1^T lo
__device__ __nv_bfloat16 g_wh2[HID_CH * HID_CH];   // W2^T hi
__device__ __nv_bfloat16 g_wl2[HID_CH * HID_CH];   // W2^T lo

__device__ __forceinline__ void split_bf16(float x, unsigned short& h, unsigned short& l) {
    __nv_bfloat16 hb = __float2bfloat16_rn(x);
    float r = x - __bfloat162float(hb);
    __nv_bfloat16 lb = __float2bfloat16_rn(r);
    h = __bfloat16_as_ushort(hb);
    l = __bfloat16_as_ushort(lb);
}

// pack 4 f32 -> (uint2 hi, uint2 lo) of bf16
__device__ __forceinline__ void split4(float4 v, uint2& hi, uint2& lo) {
    unsigned short h0, h1, h2, h3, l0, l1, l2, l3;
    split_bf16(v.x, h0, l0); split_bf16(v.y, h1, l1);
    split_bf16(v.z, h2, l2); split_bf16(v.w, h3, l3);
    hi = make_uint2((uint32_t)h0 | ((uint32_t)h1 << 16), (uint32_t)h2 | ((uint32_t)h3 << 16));
    lo = make_uint2((uint32_t)l0 | ((uint32_t)l1 << 16), (uint32_t)l2 | ((uint32_t)l3 << 16));
}

// ---------------- histogram of in-degrees (real edges only) ----------------
__global__ void hist_kernel(const int* __restrict__ dst) {
    int i = blockIdx.x * blockDim.x + threadIdx.x;
    if (i < N_EDGES) atomicAdd(&g_cnt[dst[i]], 1);
}

// ---------------- single-block scan -> rowptr, cursor, dinv; re-zeroes g_cnt ----------------
__global__ void scan_kernel() {
    __shared__ int part[1024];
    const int tid = threadIdx.x;
    const int chunk = (N_NODES + 1023) / 1024;   // 49
    int start = tid * chunk;
    int end = start + chunk; if (end > N_NODES) end = N_NODES;
    int s = 0;
    for (int i = start; i < end; i++) s += g_cnt[i];
    part[tid] = s;
    __syncthreads();
    for (int off = 1; off < 1024; off <<= 1) {
        int v = 0;
        if (tid >= off) v = part[tid - off];
        __syncthreads();
        part[tid] += v;
        __syncthreads();
    }
    int run = (tid == 0) ? 0 : part[tid - 1];
    for (int i = start; i < end; i++) {
        int c = g_cnt[i];
        g_cnt[i] = 0;                           // ready for next call
        g_rowptr[i] = run;
        g_cursor[i] = run;
        g_dinv[i] = rsqrtf((float)(c + 1));     // +1 self-loop
        run += c;
    }
    if (tid == 1023) g_rowptr[N_NODES] = part[1023];
}

// ---------------- fill CSR (src indices grouped by dst) ----------------
__global__ void fill_kernel(const int* __restrict__ src,
                            const int* __restrict__ dst) {
    int i = blockIdx.x * blockDim.x + threadIdx.x;
    if (i < N_EDGES) {
        int d = dst[i];
        int pos = atomicAdd(&g_cursor[d], 1);
        g_csrsrc[pos] = src[i];
    }
}

// ---------------- W split+transpose for BOTH layers in one launch ----------------
__global__ void split_w_both(const float* __restrict__ W1,
                             const float* __restrict__ W2) {
    int i = blockIdx.x * blockDim.x + threadIdx.x;   // 32768
    unsigned short h, l;
    if (i < 16384) {
        int k = i >> 7, n = i & 127;
        split_bf16(W1[i], h, l);
        g_wh1[n * 128 + k] = __ushort_as_bfloat16(h);
        g_wl1[n * 128 + k] = __ushort_as_bfloat16(l);
    } else {
        int j = i - 16384;
        int k = j >> 7, n = j & 127;
        split_bf16(W2[j], h, l);
        g_wh2[n * 128 + k] = __ushort_as_bfloat16(h);
        g_wl2[n * 128 + k] = __ushort_as_bfloat16(l);
    }
}

// ---------------- x split: f32 [N,128] -> bf16 planes g_xh/g_xl ----------------
__global__ void xsplit_kernel(const float* __restrict__ x) {
    int i = blockIdx.x * blockDim.x + threadIdx.x;   // 1.6M float4
    if (i < N_NODES * 32) {
        float4 v = ((const float4*)x)[i];
        uint2 hi, lo;
        split4(v, hi, lo);
        ((uint2*)g_xh)[i] = hi;
        ((uint2*)g_xl)[i] = lo;
    }
}

// ============ tensor-core GEMM via wmma on pre-split bf16 planes: C = A @ W ============
// 64x64 output tile per CTA, 256 threads = 8 warps in a 4(M)x2(N) grid, 16x32/warp.
// 3 passes (Ah*Bh + Ah*Bl + Al*Bh), fp32 accumulators. smem 69.6KB -> 3 CTAs/SM (24 warps).
// Full tiles store accumulators DIRECTLY to global; ragged tail stages via smem.
#define KP 136                                  // padded K stride in bf16 elements
// smem: Ah(64*KP) Al(64*KP) Bh(64*KP) Bl(64*KP) bf16 = 69632 B
#define SMEM_TC (4 * 64 * KP * 2)

__global__ __launch_bounds__(256, 3)
void gemm_tc(const __nv_bfloat16* __restrict__ Ahg,
             const __nv_bfloat16* __restrict__ Alg,
             const __nv_bfloat16* __restrict__ wh,
             const __nv_bfloat16* __restrict__ wl,
             float* __restrict__ C, int M) {
    extern __shared__ char smc[];
    __nv_bfloat16* Ah = (__nv_bfloat16*)smc;
    __nv_bfloat16* Al = Ah + 64 * KP;
    __nv_bfloat16* Bh = Al + 64 * KP;
    __nv_bfloat16* Bl = Bh + 64 * KP;

    const int tid = threadIdx.x;
    const int row0 = (blockIdx.x >> 1) * 64;
    const int n0   = (blockIdx.x & 1) * 64;     // N half: 0 or 64

    // ---- stage A: pure copy of pre-split planes (row = 16 uint4 of bf16) ----
    {
        const uint4* ah4 = (const uint4*)Ahg;
        const uint4* al4 = (const uint4*)Alg;
        const uint4 z = make_uint4(0, 0, 0, 0);
        for (int idx = tid; idx < 64 * 16; idx += 256) {
            int r = idx >> 4, q = idx & 15;
            int row = row0 + r;
            uint4 vh = z, vl = z;
            if (row < M) { vh = ah4[row * 16 + q]; vl = al4[row * 16 + q]; }
            *(uint4*)&Ah[r * KP + q * 8] = vh;
            *(uint4*)&Al[r * KP + q * 8] = vl;
        }
    }

    // ---- stage B: copy 64 n-rows of pre-split W^T [n][k] bf16 ----
    {
        const uint4* whg = (const uint4*)wh;     // 16 uint4 per n-row
        const uint4* wlg = (const uint4*)wl;
        for (int idx = tid; idx < 64 * 16; idx += 256) {
            int n = idx >> 4, q = idx & 15;
            *(uint4*)&Bh[n * KP + q * 8] = whg[(n0 + n) * 16 + q];
            *(uint4*)&Bl[n * KP + q * 8] = wlg[(n0 + n) * 16 + q];
        }
    }
    __syncthreads();

    // ---- wmma main loops: warp (wm, wn) owns rows wm*16..+16, cols wn*32..+32 ----
    const int wid = tid >> 5;
    const int wm = wid & 3;                      // 4 warps along M (16 rows each)
    const int wn = wid >> 2;                     // 2 warps along N (32 cols each)

    wmma::fragment<wmma::accumulator, 16, 16, 16, float> cf[2];
    wmma::fill_fragment(cf[0], 0.0f);
    wmma::fill_fragment(cf[1], 0.0f);

#pragma unroll
    for (int p = 0; p < 3; p++) {
        const __nv_bfloat16* Ap = (p == 2) ? Al : Ah;
        const __nv_bfloat16* Bp = (p == 1) ? Bl : Bh;
#pragma unroll
        for (int k8 = 0; k8 < 8; k8++) {
            wmma::fragment<wmma::matrix_a, 16, 16, 16, __nv_bfloat16, wmma::row_major> a0;
            wmma::load_matrix_sync(a0, Ap + (wm * 16) * KP + k8 * 16, KP);
            wmma::fragment<wmma::matrix_b, 16, 16, 16, __nv_bfloat16, wmma::col_major> b0, b1;
            wmma::load_matrix_sync(b0, Bp + (wn * 32 + 0)  * KP + k8 * 16, KP);
            wmma::load_matrix_sync(b1, Bp + (wn * 32 + 16) * KP + k8 * 16, KP);
            wmma::mma_sync(cf[0], a0, b0, cf[0]);
            wmma::mma_sync(cf[1], a0, b1, cf[1]);
        }
    }

    if (row0 + 64 <= M) {
        // full tile: accumulators straight to global
        wmma::store_matrix_sync(&C[(row0 + wm * 16) * 128 + n0 + wn * 32],
                                cf[0], 128, wmma::mem_row_major);
        wmma::store_matrix_sync(&C[(row0 + wm * 16) * 128 + n0 + wn * 32 + 16],
                                cf[1], 128, wmma::mem_row_major);
    } else {
        // ragged tail block: stage via smem (64x64 f32 = 16KB fits in A region), guarded writes
        __syncthreads();
        float* cs = (float*)smc;
        wmma::store_matrix_sync(&cs[(wm * 16) * 64 + wn * 32],      cf[0], 64, wmma::mem_row_major);
        wmma::store_matrix_sync(&cs[(wm * 16) * 64 + wn * 32 + 16], cf[1], 64, wmma::mem_row_major);
        __syncthreads();
        float4* C4 = (float4*)C;
        const float4* cs4 = (const float4*)cs;
        for (int idx = tid; idx < 64 * 16; idx += 256) {
            int r = idx >> 4, cq = idx & 15;
            int row = row0 + r;
            if (row < M) C4[row * 32 + (n0 >> 2) + cq] = cs4[r * 16 + cq];
        }
    }
}

// ------------- layer-1 aggregation (dinv[s] per edge), emits PRE-SPLIT bf16 planes -------------
// val = relu(dinv[d] * (sum_s h[s]*dinv[s] + h[d]*dinv[d]) + b); writes g_ah/g_al.
__global__ void agg_scale_split_kernel(const float* __restrict__ hin,
                                       const float* __restrict__ bias) {
    int gid = blockIdx.x * blockDim.x + threadIdx.x;
    int node = gid >> 5;
    int lane = gid & 31;
    if (node >= N_NODES) return;

    const float dv = g_dinv[node];
    const float4* h4 = (const float4*)hin;

    float4 acc = __ldg(&h4[node * 32 + lane]);   // self-loop (unscaled)
    acc.x *= dv; acc.y *= dv; acc.z *= dv; acc.w *= dv;

    int e0 = g_rowptr[node];
    int e1 = g_rowptr[node + 1];
    int e = e0;
    for (; e + 8 <= e1; e += 8) {
        int si[8]; float ci[8]; float4 vi[8];
#pragma unroll
        for (int q = 0; q < 8; q++) si[q] = g_csrsrc[e + q];
#pragma unroll
        for (int q = 0; q < 8; q++) ci[q] = g_dinv[si[q]];
#pragma unroll
        for (int q = 0; q < 8; q++) vi[q] = __ldg(&h4[si[q] * 32 + lane]);
#pragma unroll
        for (int q = 0; q < 8; q++) {
            acc.x += vi[q].x * ci[q];
            acc.y += vi[q].y * ci[q];
            acc.z += vi[q].z * ci[q];
            acc.w += vi[q].w * ci[q];
        }
    }
    for (; e + 4 <= e1; e += 4) {
        int s0 = g_csrsrc[e], s1 = g_csrsrc[e + 1], s2 = g_csrsrc[e + 2], s3 = g_csrsrc[e + 3];
        float c0 = g_dinv[s0], c1 = g_dinv[s1], c2 = g_dinv[s2], c3 = g_dinv[s3];
        float4 v0 = __ldg(&h4[s0 * 32 + lane]);
        float4 v1 = __ldg(&h4[s1 * 32 + lane]);
        float4 v2 = __ldg(&h4[s2 * 32 + lane]);
        float4 v3 = __ldg(&h4[s3 * 32 + lane]);
        acc.x += v0.x * c0 + v1.x * c1 + v2.x * c2 + v3.x * c3;
        acc.y += v0.y * c0 + v1.y * c1 + v2.y * c2 + v3.y * c3;
        acc.z += v0.z * c0 + v1.z * c1 + v2.z * c2 + v3.z * c3;
        acc.w += v0.w * c0 + v1.w * c1 + v2.w * c2 + v3.w * c3;
    }
    for (; e < e1; e++) {
        int s = g_csrsrc[e];
        float c = g_dinv[s];
        float4 v = __ldg(&h4[s * 32 + lane]);
        acc.x += v.x * c; acc.y += v.y * c; acc.z += v.z * c; acc.w += v.w * c;
    }

    float4 b = ((const float4*)bias)[lane];
    acc.x = fmaxf(acc.x * dv + b.x, 0.0f);
    acc.y = fmaxf(acc.y * dv + b.y, 0.0f);
    acc.z = fmaxf(acc.z * dv + b.z, 0.0f);
    acc.w = fmaxf(acc.w * dv + b.w, 0.0f);

    uint2 hi, lo;
    split4(acc, hi, lo);
    ((uint2*)g_ah)[node * 32 + lane] = hi;
    ((uint2*)g_al)[node * 32 + lane] = lo;
}

// ------- layer-2: scaled aggregation fused with mean-pool accumulation -------
__global__ void agg_scale_pool_kernel(const float* __restrict__ hin,
                                      const float* __restrict__ bias,
                                      const int* __restrict__ batch) {
    int gid = blockIdx.x * blockDim.x + threadIdx.x;
    int node = gid >> 5;
    int lane = gid & 31;
    if (node >= N_NODES) return;

    const float dv = g_dinv[node];
    const float4* h4 = (const float4*)hin;

    float4 acc = __ldg(&h4[node * 32 + lane]);
    acc.x *= dv; acc.y *= dv; acc.z *= dv; acc.w *= dv;

    int e0 = g_rowptr[node];
    int e1 = g_rowptr[node + 1];
    int e = e0;
    for (; e + 8 <= e1; e += 8) {
        int si[8]; float ci[8]; float4 vi[8];
#pragma unroll
        for (int q = 0; q < 8; q++) si[q] = g_csrsrc[e + q];
#pragma unroll
        for (int q = 0; q < 8; q++) ci[q] = g_dinv[si[q]];
#pragma unroll
        for (int q = 0; q < 8; q++) vi[q] = __ldg(&h4[si[q] * 32 + lane]);
#pragma unroll
        for (int q = 0; q < 8; q++) {
            acc.x += vi[q].x * ci[q];
            acc.y += vi[q].y * ci[q];
            acc.z += vi[q].z * ci[q];
            acc.w += vi[q].w * ci[q];
        }
    }
    for (; e + 4 <= e1; e += 4) {
        int s0 = g_csrsrc[e], s1 = g_csrsrc[e + 1], s2 = g_csrsrc[e + 2], s3 = g_csrsrc[e + 3];
        float c0 = g_dinv[s0], c1 = g_dinv[s1], c2 = g_dinv[s2], c3 = g_dinv[s3];
        float4 v0 = __ldg(&h4[s0 * 32 + lane]);
        float4 v1 = __ldg(&h4[s1 * 32 + lane]);
        float4 v2 = __ldg(&h4[s2 * 32 + lane]);
        float4 v3 = __ldg(&h4[s3 * 32 + lane]);
        acc.x += v0.x * c0 + v1.x * c1 + v2.x * c2 + v3.x * c3;
        acc.y += v0.y * c0 + v1.y * c1 + v2.y * c2 + v3.y * c3;
        acc.z += v0.z * c0 + v1.z * c1 + v2.z * c2 + v3.z * c3;
        acc.w += v0.w * c0 + v1.w * c1 + v2.w * c2 + v3.w * c3;
    }
    for (; e < e1; e++) {
        int s = g_csrsrc[e];
        float c = g_dinv[s];
        float4 v = __ldg(&h4[s * 32 + lane]);
        acc.x += v.x * c; acc.y += v.y * c; acc.z += v.z * c; acc.w += v.w * c;
    }

    float4 b = ((const float4*)bias)[lane];
    int g = batch[node];
    float* p = &g_pool[g * 128 + lane * 4];
    atomicAdd(p + 0, fmaxf(acc.x * dv + b.x, 0.0f));
    atomicAdd(p + 1, fmaxf(acc.y * dv + b.y, 0.0f));
    atomicAdd(p + 2, fmaxf(acc.z * dv + b.z, 0.0f));
    atomicAdd(p + 3, fmaxf(acc.w * dv + b.w, 0.0f));
    if (lane == 0) atomicAdd(&g_pcnt[g], 1.0f);
}

// ---------------- final: out[512,64] = (pool/cnt) @ Wlin + blin; re-zero pool ----------------
__global__ void final_kernel(const float* __restrict__ Wlin,
                             const float* __restrict__ blin,
                             float* __restrict__ out) {
    __shared__ float ws[HID_CH * OUT_CH];
    __shared__ float bs[OUT_CH];
    for (int i = threadIdx.x; i < HID_CH * OUT_CH; i += 256) ws[i] = Wlin[i];
    if (threadIdx.x < OUT_CH) bs[threadIdx.x] = blin[threadIdx.x];
    __syncthreads();

    int t = blockIdx.x * 256 + threadIdx.x;    // block owns graphs [b*4, b*4+4)
    int g = t >> 6, o = t & 63;
    float inv = 1.0f / fmaxf(g_pcnt[g], 1.0f);
    float s = 0.0f;
#pragma unroll 8
    for (int k = 0; k < 128; k++)
        s += g_pool[g * 128 + k] * ws[k * 64 + o];
    out[t] = s * inv + bs[o];

    __syncthreads();   // all reads of this block's g_pool graphs done
    int base = blockIdx.x * 512;               // 4 graphs * 128 ch
    g_pool[base + threadIdx.x] = 0.0f;
    g_pool[base + 256 + threadIdx.x] = 0.0f;
    if (threadIdx.x < 4) g_pcnt[blockIdx.x * 4 + threadIdx.x] = 0.0f;
}

// ---------------- launch (fork-join: CSR build overlaps splits + GEMM1) ----------------
// Submission order puts gemm_tc as the 4th kernel so ncu's captured launch is the GEMM.
extern "C" void kernel_launch(void* const* d_in, const int* in_sizes, int n_in,
                              void* d_out, int out_size) {
    const float* x    = (const float*)d_in[0];
    const float* W1   = (const float*)d_in[1];
    const float* b1   = (const float*)d_in[2];
    const float* W2   = (const float*)d_in[3];
    const float* b2   = (const float*)d_in[4];
    const float* Wlin = (const float*)d_in[5];
    const float* blin = (const float*)d_in[6];
    const int* edge   = (const int*)d_in[7];     // JAX x64-disabled: int64 -> int32
    const int* batch  = (const int*)d_in[8];
    float* out = (float*)d_out;

    const int* src = edge;
    const int* dst = edge + N_EDGES;

    float *t1;
    __nv_bfloat16 *wh1, *wl1, *wh2, *wl2, *xh, *xl, *ah, *al;
    cudaGetSymbolAddress((void**)&t1, g_t1);
    cudaGetSymbolAddress((void**)&wh1, g_wh1);
    cudaGetSymbolAddress((void**)&wl1, g_wl1);
    cudaGetSymbolAddress((void**)&wh2, g_wh2);
    cudaGetSymbolAddress((void**)&wl2, g_wl2);
    cudaGetSymbolAddress((void**)&xh, g_xh);
    cudaGetSymbolAddress((void**)&xl, g_xl);
    cudaGetSymbolAddress((void**)&ah, g_ah);
    cudaGetSymbolAddress((void**)&al, g_al);

    cudaFuncSetAttribute(gemm_tc, cudaFuncAttributeMaxDynamicSharedMemorySize, SMEM_TC);

    // host-side stream/event handles, created once (no device memory involved)
    static cudaStream_t s_side = nullptr;
    static cudaEvent_t ev_fork = nullptr, ev_join = nullptr;
    if (s_side == nullptr) {
        cudaStreamCreateWithFlags(&s_side, cudaStreamNonBlocking);
        cudaEventCreateWithFlags(&ev_fork, cudaEventDisableTiming);
        cudaEventCreateWithFlags(&ev_join, cudaEventDisableTiming);
    }

    const int eb = (N_EDGES + 255) / 256;               // 2344
    const int gb = ((N_NODES + 63) / 64) * 2;           // 1564 (M-tiles x 2 N-halves)
    const int ab = (N_NODES * 32) / 256;                // 6250
    const int xb = (N_NODES * 32 + 255) / 256;          // 6250

    // fork event first so side stream is capture-joined to the origin stream
    cudaEventRecord(ev_fork, 0);
    cudaStreamWaitEvent(s_side, ev_fork, 0);

    // main: splits (1,2)
    split_w_both<<<128, 256>>>(W1, W2);
    xsplit_kernel<<<xb, 256>>>(x);
    // side: CSR chain starts (3)
    hist_kernel<<<eb, 256, 0, s_side>>>(dst);
    // main: GEMM1 (4th submitted kernel -> ncu capture target)
    gemm_tc<<<gb, 256, SMEM_TC>>>(xh, xl, wh1, wl1, t1, N_NODES);
    // side: rest of CSR chain (5,6)
    scan_kernel<<<1, 1024, 0, s_side>>>();
    fill_kernel<<<eb, 256, 0, s_side>>>(src, dst);
    cudaEventRecord(ev_join, s_side);

    // join: agg1 needs rowptr/csrsrc/dinv from the side stream
    cudaStreamWaitEvent(0, ev_join, 0);
    agg_scale_split_kernel<<<ab, 256>>>(t1, b1);        // emits g_ah/g_al planes

    gemm_tc<<<gb, 256, SMEM_TC>>>(ah, al, wh2, wl2, t1, N_NODES);
    agg_scale_pool_kernel<<<ab, 256>>>(t1, b2, batch);

    final_kernel<<<128, 256>>>(Wlin, blin, out);
}

// round 12
// speedup vs baseline: 1.1035x; 1.1035x over previous
#include <cuda_runtime.h>
#include <cuda_bf16.h>
#include <mma.h>
#include <cstdint>

using namespace nvcuda;

#define N_NODES 50000
#define N_EDGES 600000
#define IN_CH 128
#define HID_CH 128
#define OUT_CH 64
#define NUM_GRAPHS 512

// ---------------- device scratch (zero-initialized at load; every call leaves
// g_cnt / g_pool / g_pcnt zeroed again, so replays are identical) ----------------
__device__ float g_t1[N_NODES * HID_CH];       // 25.6 MB (GEMM outputs, agg gathers)
__device__ __nv_bfloat16 g_ah[N_NODES * HID_CH];  // 12.8 MB: A-plane hi for next GEMM
__device__ __nv_bfloat16 g_al[N_NODES * HID_CH];  // 12.8 MB: A-plane lo
__device__ __nv_bfloat16 g_xh[N_NODES * HID_CH];  // x split planes
__device__ __nv_bfloat16 g_xl[N_NODES * HID_CH];
__device__ int   g_cnt[N_NODES];
__device__ float g_dinv[N_NODES];
__device__ int   g_rowptr[N_NODES + 1];
__device__ int   g_cursor[N_NODES];
__device__ int   g_csrsrc[N_EDGES];
__device__ float g_pool[NUM_GRAPHS * HID_CH];
__device__ float g_pcnt[NUM_GRAPHS];
__device__ __nv_bfloat16 g_wh1[HID_CH * HID_CH];   // W1^T hi, [n][k]
__device__ __nv_bfloat16 g_wl1[HID_CH * HID_CH];   // W1^T lo
__device__ __nv_bfloat16 g_wh2[HID_CH * HID_CH];   // W2^T hi
__device__ __nv_bfloat16 g_wl2[HID_CH * HID_CH];   // W2^T lo

__device__ __forceinline__ void split_bf16(float x, unsigned short& h, unsigned short& l) {
    __nv_bfloat16 hb = __float2bfloat16_rn(x);
    float r = x - __bfloat162float(hb);
    __nv_bfloat16 lb = __float2bfloat16_rn(r);
    h = __bfloat16_as_ushort(hb);
    l = __bfloat16_as_ushort(lb);
}

// pack 4 f32 -> (uint2 hi, uint2 lo) of bf16
__device__ __forceinline__ void split4(float4 v, uint2& hi, uint2& lo) {
    unsigned short h0, h1, h2, h3, l0, l1, l2, l3;
    split_bf16(v.x, h0, l0); split_bf16(v.y, h1, l1);
    split_bf16(v.z, h2, l2); split_bf16(v.w, h3, l3);
    hi = make_uint2((uint32_t)h0 | ((uint32_t)h1 << 16), (uint32_t)h2 | ((uint32_t)h3 << 16));
    lo = make_uint2((uint32_t)l0 | ((uint32_t)l1 << 16), (uint32_t)l2 | ((uint32_t)l3 << 16));
}

// ---------------- histogram of in-degrees (real edges only) ----------------
__global__ void hist_kernel(const int* __restrict__ dst) {
    int i = blockIdx.x * blockDim.x + threadIdx.x;
    if (i < N_EDGES) atomicAdd(&g_cnt[dst[i]], 1);
}

// ---------------- single-block scan -> rowptr, cursor, dinv; re-zeroes g_cnt ----------------
__global__ void scan_kernel() {
    __shared__ int part[1024];
    const int tid = threadIdx.x;
    const int chunk = (N_NODES + 1023) / 1024;   // 49
    int start = tid * chunk;
    int end = start + chunk; if (end > N_NODES) end = N_NODES;
    int s = 0;
    for (int i = start; i < end; i++) s += g_cnt[i];
    part[tid] = s;
    __syncthreads();
    for (int off = 1; off < 1024; off <<= 1) {
        int v = 0;
        if (tid >= off) v = part[tid - off];
        __syncthreads();
        part[tid] += v;
        __syncthreads();
    }
    int run = (tid == 0) ? 0 : part[tid - 1];
    for (int i = start; i < end; i++) {
        int c = g_cnt[i];
        g_cnt[i] = 0;                           // ready for next call
        g_rowptr[i] = run;
        g_cursor[i] = run;
        g_dinv[i] = rsqrtf((float)(c + 1));     // +1 self-loop
        run += c;
    }
    if (tid == 1023) g_rowptr[N_NODES] = part[1023];
}

// ---------------- fill CSR (src indices grouped by dst) ----------------
__global__ void fill_kernel(const int* __restrict__ src,
                            const int* __restrict__ dst) {
    int i = blockIdx.x * blockDim.x + threadIdx.x;
    if (i < N_EDGES) {
        int d = dst[i];
        int pos = atomicAdd(&g_cursor[d], 1);
        g_csrsrc[pos] = src[i];
    }
}

// ---------------- W split+transpose for BOTH layers in one launch ----------------
__global__ void split_w_both(const float* __restrict__ W1,
                             const float* __restrict__ W2) {
    int i = blockIdx.x * blockDim.x + threadIdx.x;   // 32768
    unsigned short h, l;
    if (i < 16384) {
        int k = i >> 7, n = i & 127;
        split_bf16(W1[i], h, l);
        g_wh1[n * 128 + k] = __ushort_as_bfloat16(h);
        g_wl1[n * 128 + k] = __ushort_as_bfloat16(l);
    } else {
        int j = i - 16384;
        int k = j >> 7, n = j & 127;
        split_bf16(W2[j], h, l);
        g_wh2[n * 128 + k] = __ushort_as_bfloat16(h);
        g_wl2[n * 128 + k] = __ushort_as_bfloat16(l);
    }
}

// ---------------- x split: f32 [N,128] -> bf16 planes g_xh/g_xl ----------------
__global__ void xsplit_kernel(const float* __restrict__ x) {
    int i = blockIdx.x * blockDim.x + threadIdx.x;   // 1.6M float4
    if (i < N_NODES * 32) {
        float4 v = ((const float4*)x)[i];
        uint2 hi, lo;
        split4(v, hi, lo);
        ((uint2*)g_xh)[i] = hi;
        ((uint2*)g_xl)[i] = lo;
    }
}

// ============ tensor-core GEMM via wmma on pre-split bf16 planes: C = A @ W ============
// 64x128 output tile per CTA, 256 threads = 8 warps in a 2(M)x4(N) grid, 32x32/warp.
// FUSED k-loop: per k-step load ah0,ah1,al0,al1,bh0,bh1,bl0,bl1 (8 LDSM groups) and
// issue all 12 MMAs (Ah*Bh + Ah*Bl + Al*Bh over the 2x2 accum grid) -> 1.5 MMA/load.
// Full tiles store accumulators DIRECTLY to global; ragged tail stages via smem.
#define KP 136                                  // padded K stride in bf16 elements
// smem: Ah(64*KP) Al(64*KP) Bh(128*KP) Bl(128*KP) bf16 = 104448 B -> 2 CTAs/SM
#define SMEM_TC ((64 + 64 + 128 + 128) * KP * 2)

__global__ __launch_bounds__(256, 2)
void gemm_tc(const __nv_bfloat16* __restrict__ Ahg,
             const __nv_bfloat16* __restrict__ Alg,
             const __nv_bfloat16* __restrict__ wh,
             const __nv_bfloat16* __restrict__ wl,
             float* __restrict__ C, int M) {
    extern __shared__ char smc[];
    __nv_bfloat16* Ah = (__nv_bfloat16*)smc;
    __nv_bfloat16* Al = Ah + 64 * KP;
    __nv_bfloat16* Bh = Al + 64 * KP;
    __nv_bfloat16* Bl = Bh + 128 * KP;

    const int tid = threadIdx.x;
    const int row0 = blockIdx.x * 64;

    // ---- stage A: pure copy of pre-split planes (row = 16 uint4 of bf16) ----
    {
        const uint4* ah4 = (const uint4*)Ahg;
        const uint4* al4 = (const uint4*)Alg;
        const uint4 z = make_uint4(0, 0, 0, 0);
        for (int idx = tid; idx < 64 * 16; idx += 256) {
            int r = idx >> 4, q = idx & 15;
            int row = row0 + r;
            uint4 vh = z, vl = z;
            if (row < M) { vh = ah4[row * 16 + q]; vl = al4[row * 16 + q]; }
            *(uint4*)&Ah[r * KP + q * 8] = vh;
            *(uint4*)&Al[r * KP + q * 8] = vl;
        }
    }

    // ---- stage B: plain copy of pre-split W^T [n][k] bf16 ----
    {
        const uint4* whg = (const uint4*)wh;     // 2048 uint4 (8 bf16 each)
        const uint4* wlg = (const uint4*)wl;
        for (int idx = tid; idx < 2048; idx += 256) {
            int n = idx >> 4, q = idx & 15;
            *(uint4*)&Bh[n * KP + q * 8] = whg[idx];
            *(uint4*)&Bl[n * KP + q * 8] = wlg[idx];
        }
    }
    __syncthreads();

    // ---- fused wmma main loop: warp (wm, wn) owns rows wm*32..+32, cols wn*32..+32 ----
    const int wid = tid >> 5;
    const int wm = wid & 1;
    const int wn = wid >> 1;

    wmma::fragment<wmma::accumulator, 16, 16, 16, float> cf[2][2];
#pragma unroll
    for (int i = 0; i < 2; i++)
#pragma unroll
        for (int j = 0; j < 2; j++) wmma::fill_fragment(cf[i][j], 0.0f);

#pragma unroll
    for (int k8 = 0; k8 < 8; k8++) {
        wmma::fragment<wmma::matrix_a, 16, 16, 16, __nv_bfloat16, wmma::row_major> ah0, ah1, al0, al1;
        wmma::load_matrix_sync(ah0, Ah + (wm * 32 + 0)  * KP + k8 * 16, KP);
        wmma::load_matrix_sync(ah1, Ah + (wm * 32 + 16) * KP + k8 * 16, KP);
        wmma::load_matrix_sync(al0, Al + (wm * 32 + 0)  * KP + k8 * 16, KP);
        wmma::load_matrix_sync(al1, Al + (wm * 32 + 16) * KP + k8 * 16, KP);
        wmma::fragment<wmma::matrix_b, 16, 16, 16, __nv_bfloat16, wmma::col_major> bh0, bh1, bl0, bl1;
        wmma::load_matrix_sync(bh0, Bh + (wn * 32 + 0)  * KP + k8 * 16, KP);
        wmma::load_matrix_sync(bh1, Bh + (wn * 32 + 16) * KP + k8 * 16, KP);
        wmma::load_matrix_sync(bl0, Bl + (wn * 32 + 0)  * KP + k8 * 16, KP);
        wmma::load_matrix_sync(bl1, Bl + (wn * 32 + 16) * KP + k8 * 16, KP);

        // pass hh
        wmma::mma_sync(cf[0][0], ah0, bh0, cf[0][0]);
        wmma::mma_sync(cf[0][1], ah0, bh1, cf[0][1]);
        wmma::mma_sync(cf[1][0], ah1, bh0, cf[1][0]);
        wmma::mma_sync(cf[1][1], ah1, bh1, cf[1][1]);
        // pass hl
        wmma::mma_sync(cf[0][0], ah0, bl0, cf[0][0]);
        wmma::mma_sync(cf[0][1], ah0, bl1, cf[0][1]);
        wmma::mma_sync(cf[1][0], ah1, bl0, cf[1][0]);
        wmma::mma_sync(cf[1][1], ah1, bl1, cf[1][1]);
        // pass lh
        wmma::mma_sync(cf[0][0], al0, bh0, cf[0][0]);
        wmma::mma_sync(cf[0][1], al0, bh1, cf[0][1]);
        wmma::mma_sync(cf[1][0], al1, bh0, cf[1][0]);
        wmma::mma_sync(cf[1][1], al1, bh1, cf[1][1]);
    }

    if (row0 + 64 <= M) {
        // full tile: accumulators straight to global
#pragma unroll
        for (int i = 0; i < 2; i++)
#pragma unroll
            for (int j = 0; j < 2; j++)
                wmma::store_matrix_sync(&C[(row0 + wm * 32 + i * 16) * 128 + wn * 32 + j * 16],
                                        cf[i][j], 128, wmma::mem_row_major);
    } else {
        // ragged tail block: stage via smem, guarded writes
        __syncthreads();
        float* cs = (float*)smc;                 // 64x128 f32 = 32KB
#pragma unroll
        for (int i = 0; i < 2; i++)
#pragma unroll
            for (int j = 0; j < 2; j++)
                wmma::store_matrix_sync(&cs[(wm * 32 + i * 16) * 128 + wn * 32 + j * 16],
                                        cf[i][j], 128, wmma::mem_row_major);
        __syncthreads();
        float4* C4 = (float4*)C;
        const float4* cs4 = (const float4*)cs;
        for (int idx = tid; idx < 64 * 32; idx += 256) {
            int r = idx >> 5, cq = idx & 31;
            int row = row0 + r;
            if (row < M) C4[row * 32 + cq] = cs4[r * 32 + cq];
        }
    }
}

// ------------- layer-1 aggregation (dinv[s] per edge), emits PRE-SPLIT bf16 planes -------------
// val = relu(dinv[d] * (sum_s h[s]*dinv[s] + h[d]*dinv[d]) + b); writes g_ah/g_al.
__global__ void agg_scale_split_kernel(const float* __restrict__ hin,
                                       const float* __restrict__ bias) {
    int gid = blockIdx.x * blockDim.x + threadIdx.x;
    int node = gid >> 5;
    int lane = gid & 31;
    if (node >= N_NODES) return;

    const float dv = g_dinv[node];
    const float4* h4 = (const float4*)hin;

    float4 acc = __ldg(&h4[node * 32 + lane]);   // self-loop (unscaled)
    acc.x *= dv; acc.y *= dv; acc.z *= dv; acc.w *= dv;

    int e0 = g_rowptr[node];
    int e1 = g_rowptr[node + 1];
    int e = e0;
    for (; e + 8 <= e1; e += 8) {
        int si[8]; float ci[8]; float4 vi[8];
#pragma unroll
        for (int q = 0; q < 8; q++) si[q] = g_csrsrc[e + q];
#pragma unroll
        for (int q = 0; q < 8; q++) ci[q] = g_dinv[si[q]];
#pragma unroll
        for (int q = 0; q < 8; q++) vi[q] = __ldg(&h4[si[q] * 32 + lane]);
#pragma unroll
        for (int q = 0; q < 8; q++) {
            acc.x += vi[q].x * ci[q];
            acc.y += vi[q].y * ci[q];
            acc.z += vi[q].z * ci[q];
            acc.w += vi[q].w * ci[q];
        }
    }
    for (; e + 4 <= e1; e += 4) {
        int s0 = g_csrsrc[e], s1 = g_csrsrc[e + 1], s2 = g_csrsrc[e + 2], s3 = g_csrsrc[e + 3];
        float c0 = g_dinv[s0], c1 = g_dinv[s1], c2 = g_dinv[s2], c3 = g_dinv[s3];
        float4 v0 = __ldg(&h4[s0 * 32 + lane]);
        float4 v1 = __ldg(&h4[s1 * 32 + lane]);
        float4 v2 = __ldg(&h4[s2 * 32 + lane]);
        float4 v3 = __ldg(&h4[s3 * 32 + lane]);
        acc.x += v0.x * c0 + v1.x * c1 + v2.x * c2 + v3.x * c3;
        acc.y += v0.y * c0 + v1.y * c1 + v2.y * c2 + v3.y * c3;
        acc.z += v0.z * c0 + v1.z * c1 + v2.z * c2 + v3.z * c3;
        acc.w += v0.w * c0 + v1.w * c1 + v2.w * c2 + v3.w * c3;
    }
    for (; e < e1; e++) {
        int s = g_csrsrc[e];
        float c = g_dinv[s];
        float4 v = __ldg(&h4[s * 32 + lane]);
        acc.x += v.x * c; acc.y += v.y * c; acc.z += v.z * c; acc.w += v.w * c;
    }

    float4 b = ((const float4*)bias)[lane];
    acc.x = fmaxf(acc.x * dv + b.x, 0.0f);
    acc.y = fmaxf(acc.y * dv + b.y, 0.0f);
    acc.z = fmaxf(acc.z * dv + b.z, 0.0f);
    acc.w = fmaxf(acc.w * dv + b.w, 0.0f);

    uint2 hi, lo;
    split4(acc, hi, lo);
    ((uint2*)g_ah)[node * 32 + lane] = hi;
    ((uint2*)g_al)[node * 32 + lane] = lo;
}

// ------- layer-2: scaled aggregation fused with mean-pool accumulation -------
__global__ void agg_scale_pool_kernel(const float* __restrict__ hin,
                                      const float* __restrict__ bias,
                                      const int* __restrict__ batch) {
    int gid = blockIdx.x * blockDim.x + threadIdx.x;
    int node = gid >> 5;
    int lane = gid & 31;
    if (node >= N_NODES) return;

    const float dv = g_dinv[node];
    const float4* h4 = (const float4*)hin;

    float4 acc = __ldg(&h4[node * 32 + lane]);
    acc.x *= dv; acc.y *= dv; acc.z *= dv; acc.w *= dv;

    int e0 = g_rowptr[node];
    int e1 = g_rowptr[node + 1];
    int e = e0;
    for (; e + 8 <= e1; e += 8) {
        int si[8]; float ci[8]; float4 vi[8];
#pragma unroll
        for (int q = 0; q < 8; q++) si[q] = g_csrsrc[e + q];
#pragma unroll
        for (int q = 0; q < 8; q++) ci[q] = g_dinv[si[q]];
#pragma unroll
        for (int q = 0; q < 8; q++) vi[q] = __ldg(&h4[si[q] * 32 + lane]);
#pragma unroll
        for (int q = 0; q < 8; q++) {
            acc.x += vi[q].x * ci[q];
            acc.y += vi[q].y * ci[q];
            acc.z += vi[q].z * ci[q];
            acc.w += vi[q].w * ci[q];
        }
    }
    for (; e + 4 <= e1; e += 4) {
        int s0 = g_csrsrc[e], s1 = g_csrsrc[e + 1], s2 = g_csrsrc[e + 2], s3 = g_csrsrc[e + 3];
        float c0 = g_dinv[s0], c1 = g_dinv[s1], c2 = g_dinv[s2], c3 = g_dinv[s3];
        float4 v0 = __ldg(&h4[s0 * 32 + lane]);
        float4 v1 = __ldg(&h4[s1 * 32 + lane]);
        float4 v2 = __ldg(&h4[s2 * 32 + lane]);
        float4 v3 = __ldg(&h4[s3 * 32 + lane]);
        acc.x += v0.x * c0 + v1.x * c1 + v2.x * c2 + v3.x * c3;
        acc.y += v0.y * c0 + v1.y * c1 + v2.y * c2 + v3.y * c3;
        acc.z += v0.z * c0 + v1.z * c1 + v2.z * c2 + v3.z * c3;
        acc.w += v0.w * c0 + v1.w * c1 + v2.w * c2 + v3.w * c3;
    }
    for (; e < e1; e++) {
        int s = g_csrsrc[e];
        float c = g_dinv[s];
        float4 v = __ldg(&h4[s * 32 + lane]);
        acc.x += v.x * c; acc.y += v.y * c; acc.z += v.z * c; acc.w += v.w * c;
    }

    float4 b = ((const float4*)bias)[lane];
    int g = batch[node];
    float* p = &g_pool[g * 128 + lane * 4];
    atomicAdd(p + 0, fmaxf(acc.x * dv + b.x, 0.0f));
    atomicAdd(p + 1, fmaxf(acc.y * dv + b.y, 0.0f));
    atomicAdd(p + 2, fmaxf(acc.z * dv + b.z, 0.0f));
    atomicAdd(p + 3, fmaxf(acc.w * dv + b.w, 0.0f));
    if (lane == 0) atomicAdd(&g_pcnt[g], 1.0f);
}

// ---------------- final: out[512,64] = (pool/cnt) @ Wlin + blin; re-zero pool ----------------
__global__ void final_kernel(const float* __restrict__ Wlin,
                             const float* __restrict__ blin,
                             float* __restrict__ out) {
    __shared__ float ws[HID_CH * OUT_CH];
    __shared__ float bs[OUT_CH];
    for (int i = threadIdx.x; i < HID_CH * OUT_CH; i += 256) ws[i] = Wlin[i];
    if (threadIdx.x < OUT_CH) bs[threadIdx.x] = blin[threadIdx.x];
    __syncthreads();

    int t = blockIdx.x * 256 + threadIdx.x;    // block owns graphs [b*4, b*4+4)
    int g = t >> 6, o = t & 63;
    float inv = 1.0f / fmaxf(g_pcnt[g], 1.0f);
    float s = 0.0f;
#pragma unroll 8
    for (int k = 0; k < 128; k++)
        s += g_pool[g * 128 + k] * ws[k * 64 + o];
    out[t] = s * inv + bs[o];

    __syncthreads();   // all reads of this block's g_pool graphs done
    int base = blockIdx.x * 512;               // 4 graphs * 128 ch
    g_pool[base + threadIdx.x] = 0.0f;
    g_pool[base + 256 + threadIdx.x] = 0.0f;
    if (threadIdx.x < 4) g_pcnt[blockIdx.x * 4 + threadIdx.x] = 0.0f;
}

// ---------------- launch (fork-join: CSR build overlaps splits + GEMM1) ----------------
// Submission order keeps gemm_tc as the 4th kernel so ncu's captured launch is the GEMM.
extern "C" void kernel_launch(void* const* d_in, const int* in_sizes, int n_in,
                              void* d_out, int out_size) {
    const float* x    = (const float*)d_in[0];
    const float* W1   = (const float*)d_in[1];
    const float* b1   = (const float*)d_in[2];
    const float* W2   = (const float*)d_in[3];
    const float* b2   = (const float*)d_in[4];
    const float* Wlin = (const float*)d_in[5];
    const float* blin = (const float*)d_in[6];
    const int* edge   = (const int*)d_in[7];     // JAX x64-disabled: int64 -> int32
    const int* batch  = (const int*)d_in[8];
    float* out = (float*)d_out;

    const int* src = edge;
    const int* dst = edge + N_EDGES;

    float *t1;
    __nv_bfloat16 *wh1, *wl1, *wh2, *wl2, *xh, *xl, *ah, *al;
    cudaGetSymbolAddress((void**)&t1, g_t1);
    cudaGetSymbolAddress((void**)&wh1, g_wh1);
    cudaGetSymbolAddress((void**)&wl1, g_wl1);
    cudaGetSymbolAddress((void**)&wh2, g_wh2);
    cudaGetSymbolAddress((void**)&wl2, g_wl2);
    cudaGetSymbolAddress((void**)&xh, g_xh);
    cudaGetSymbolAddress((void**)&xl, g_xl);
    cudaGetSymbolAddress((void**)&ah, g_ah);
    cudaGetSymbolAddress((void**)&al, g_al);

    cudaFuncSetAttribute(gemm_tc, cudaFuncAttributeMaxDynamicSharedMemorySize, SMEM_TC);

    // host-side stream/event handles, created once (no device memory involved)
    static cudaStream_t s_side = nullptr;
    static cudaEvent_t ev_fork = nullptr, ev_join = nullptr;
    if (s_side == nullptr) {
        cudaStreamCreateWithFlags(&s_side, cudaStreamNonBlocking);
        cudaEventCreateWithFlags(&ev_fork, cudaEventDisableTiming);
        cudaEventCreateWithFlags(&ev_join, cudaEventDisableTiming);
    }

    const int eb = (N_EDGES + 255) / 256;               // 2344
    const int gb = (N_NODES + 63) / 64;                 // 782
    const int ab = (N_NODES * 32) / 256;                // 6250
    const int xb = (N_NODES * 32 + 255) / 256;          // 6250

    // fork event first so side stream is capture-joined to the origin stream
    cudaEventRecord(ev_fork, 0);
    cudaStreamWaitEvent(s_side, ev_fork, 0);

    // main: splits (1,2)
    split_w_both<<<128, 256>>>(W1, W2);
    xsplit_kernel<<<xb, 256>>>(x);
    // side: CSR chain starts (3)
    hist_kernel<<<eb, 256, 0, s_side>>>(dst);
    // main: GEMM1 (4th submitted kernel -> ncu capture target)
    gemm_tc<<<gb, 256, SMEM_TC>>>(xh, xl, wh1, wl1, t1, N_NODES);
    // side: rest of CSR chain (5,6)
    scan_kernel<<<1, 1024, 0, s_side>>>();
    fill_kernel<<<eb, 256, 0, s_side>>>(src, dst);
    cudaEventRecord(ev_join, s_side);

    // join: agg1 needs rowptr/csrsrc/dinv from the side stream
    cudaStreamWaitEvent(0, ev_join, 0);
    agg_scale_split_kernel<<<ab, 256>>>(t1, b1);        // emits g_ah/g_al planes

    gemm_tc<<<gb, 256, SMEM_TC>>>(ah, al, wh2, wl2, t1, N_NODES);
    agg_scale_pool_kernel<<<ab, 256>>>(t1, b2, batch);

    final_kernel<<<128, 256>>>(Wlin, blin, out);
}